// round 15
// baseline (speedup 1.0000x reference)
#include <cuda_runtime.h>

// RoIAlign, NCHW fp32, OUT 7x7, sampling_ratio 2, scale 0.25
// features: (2, 256, 200, 304), rois: (512, 5), out: (512, 256, 7, 7)
//
// Single kernel. Block = (roi, 32-channel group), 8 warps; warp = 4 channels.
// Block prologue precomputes the ROI plan into shared memory:
//   s_x[32]   : per-lane (column, x-weight) — lanes 0..13 corner x0,
//               lanes 16..29 corner x0+1; idle lanes (14,15,30,31) reuse
//               sample 13's column with weight 0 (no extra cache lines).
//   s_plan[14]: per y-sample (rowT*W, rowB*W, wT, wB), 0.25 mean and
//               y-validity folded into the weights
//   s_pack    : 14 x 2-bit transition codes in one int:
//               0 = same rows as prev, 1 = shift down one row, 2 = jump
// Hot loop: two-row register-cache walk with END-OF-ITERATION advance.
// After sample i's FMAs (vA/vB dead), the cache advances for sample i+1:
// code 1 moves vB->vA, code 2 loads the new top row into vA, and the new
// bottom row is loaded UNCONDITIONALLY into vB (code 0 re-reads the
// identical L1-hot line — round 14's proven trick). This removes the
// separate prefetch buffer (pf) and its per-iteration hand-off copies,
// cutting register pressure while keeping loads issued a full iteration
// (including the shfl/STG epilogue) before consumption.
// Epilogue: dual-channel shuffle reduction — one shfl_xor(16) carries two
// channels' corner sums simultaneously, one shfl_xor(1) folds x-pairs,
// one STG writes both channels' bins.

namespace {
constexpr int OUT_H = 7;
constexpr int OUT_W = 7;
constexpr int C     = 256;
constexpr int H     = 200;
constexpr int W     = 304;
constexpr int R     = 512;
constexpr float SCALE = 0.25f;

constexpr int WARPS_PER_BLOCK = 8;
constexpr int GROUPS          = 8;                          // gridDim.y
constexpr int WARPS_PER_ROI   = WARPS_PER_BLOCK * GROUPS;   // 64
constexpr int CH_PER_WARP     = C / WARPS_PER_ROI;          // 4
constexpr int PLANE           = H * W;                      // 60800
constexpr int NSAMP           = OUT_H * 2;                  // 14 y-samples
}

__global__ __launch_bounds__(WARPS_PER_BLOCK * 32)
void roi_align_kernel(const float* __restrict__ feat,
                      const float* __restrict__ rois,
                      float* __restrict__ out)
{
    __shared__ float2 s_x[32];        // per-lane (col as int bits, wx)
    __shared__ float4 s_plan[NSAMP];  // (offT bits, offB bits, wT, wB)
    __shared__ int    s_pack;         // 2-bit codes, sample i at bits [2i,2i+2)
    __shared__ int    s_b;

    const int r    = blockIdx.x;
    const int tid  = threadIdx.x;
    const int lane = tid & 31;

    // ---------- prologue: build the plan ----------
    if (tid < 96) {
        const float rx1 = rois[r * 5 + 1] * SCALE - 0.5f;
        const float ry1 = rois[r * 5 + 2] * SCALE - 0.5f;
        const float rx2 = rois[r * 5 + 3] * SCALE - 0.5f;
        const float ry2 = rois[r * 5 + 4] * SCALE - 0.5f;
        const float bin_w = (rx2 - rx1) * (1.0f / OUT_W);
        const float bin_h = (ry2 - ry1) * (1.0f / OUT_H);

        if (tid == 0) s_b = (int)rois[r * 5 + 0];

        if (tid < NSAMP) {
            const int i = tid;   // y-sample: oy = i>>1, g = i&1
            float yg = ry1 + ((float)(i >> 1) + 0.25f + 0.5f * (float)(i & 1)) * bin_h;
            float vy = ((yg > -1.0f) && (yg < (float)H)) ? 1.0f : 0.0f;
            float yc = fminf(fmaxf(yg, 0.0f), (float)(H - 1));
            int   t  = (int)yc;
            float ly = yc - (float)t;
            int   bb = min(t + 1, H - 1);
            s_plan[i] = make_float4(__int_as_float(t * W), __int_as_float(bb * W),
                                    0.25f * (1.0f - ly) * vy, 0.25f * ly * vy);
        }

        if (tid >= 32 && tid < 64) {
            const int  l   = tid - 32;     // x-table entry
            const int  sx  = l & 15;       // 0..15
            const bool hi  = l >= 16;
            // Idle lanes (sx 14,15) reuse sample 13's column (weight 0).
            const int  sxe = min(sx, 13);
            float x  = rx1 + ((float)(sxe >> 1) + ((float)(sxe & 1) + 0.5f) * 0.5f) * bin_w;
            float vx = ((x > -1.0f) && (x < (float)W) && (sx < 14)) ? 1.0f : 0.0f;
            float xc = fminf(fmaxf(x, 0.0f), (float)(W - 1));
            int   x0 = (int)xc;
            float lx = xc - (float)x0;
            float2 e = hi ? make_float2(__int_as_float(min(x0 + 1, W - 1)), lx * vx)
                          : make_float2(__int_as_float(x0), (1.0f - lx) * vx);
            s_x[l] = e;
        }

        if (tid == 64) {
            // serial recompute of the 14 transition codes into one bitmask
            int pack = 0;
            int prevT = -0x40000000, prevB = -0x40000000;
            #pragma unroll
            for (int i = 0; i < NSAMP; ++i) {
                float yg = ry1 + ((float)(i >> 1) + 0.25f + 0.5f * (float)(i & 1)) * bin_h;
                float yc = fminf(fmaxf(yg, 0.0f), (float)(H - 1));
                int   t  = (int)yc;
                int   bb = min(t + 1, H - 1);
                int code = (t == prevT) ? 0 : ((t == prevB) ? 1 : 2);
                pack |= code << (2 * i);
                prevT = t; prevB = bb;
            }
            s_pack = pack;
        }
    }
    __syncthreads();

    // ---------- hot loop ----------
    const int warpId = tid >> 5;
    const int wroi   = blockIdx.y * WARPS_PER_BLOCK + warpId;  // 0..63
    const int c0     = wroi * CH_PER_WARP;

    const float2 xe   = s_x[lane];
    const int    col  = __float_as_int(xe.x);
    const float  wx   = xe.y;
    const int    pack = s_pack;

    const int  sx     = lane & 15;
    const bool hiHalf = lane >= 16;
    const bool doSt   = (sx < 14) && ((sx & 1) == 0);   // 14 store lanes

    const float* pb = feat + ((size_t)s_b * C + c0) * PLANE + col;
    // per-lane output base: channel parity = half, bin = sx>>1
    float* outB = out + ((size_t)r * C + c0 + (hiHalf ? 1 : 0)) * (OUT_H * OUT_W)
                      + (sx >> 1);

    float vA[CH_PER_WARP], vB[CH_PER_WARP];
    float bacc[CH_PER_WARP];

    // preload sample 0's rows (code(0) == 2 always): top -> vA, bottom -> vB
    {
        const int offT0 = __float_as_int(s_plan[0].x);
        const int offB0 = __float_as_int(s_plan[0].y);
        #pragma unroll
        for (int cc = 0; cc < CH_PER_WARP; ++cc)
            vA[cc] = __ldg(pb + (size_t)cc * PLANE + offT0);
        #pragma unroll
        for (int cc = 0; cc < CH_PER_WARP; ++cc)
            vB[cc] = __ldg(pb + (size_t)cc * PLANE + offB0);
    }

    #pragma unroll
    for (int i = 0; i < NSAMP; ++i) {
        const float4 pe = s_plan[i];

        // consume: pure FMAs (cache already holds sample i's rows)
        if ((i & 1) == 0) {
            #pragma unroll
            for (int cc = 0; cc < CH_PER_WARP; ++cc)
                bacc[cc] = pe.z * vA[cc] + pe.w * vB[cc];
        } else {
            #pragma unroll
            for (int cc = 0; cc < CH_PER_WARP; ++cc)
                bacc[cc] += pe.z * vA[cc] + pe.w * vB[cc];
        }

        // advance the cache for sample i+1 (vA/vB dead past the FMAs):
        // loads get the rest of this iteration (incl. epilogue) to land.
        if (i + 1 < NSAMP) {
            const int codeN = (pack >> (2 * (i + 1))) & 3;
            const float4 pn = s_plan[i + 1];
            if (codeN == 2) {
                const int offTn = __float_as_int(pn.x);
                #pragma unroll
                for (int cc = 0; cc < CH_PER_WARP; ++cc)
                    vA[cc] = __ldg(pb + (size_t)cc * PLANE + offTn);
            } else if (codeN == 1) {
                #pragma unroll
                for (int cc = 0; cc < CH_PER_WARP; ++cc)
                    vA[cc] = vB[cc];
            }
            // unconditional bottom-row load (code 0 re-reads the same line)
            const int offBn = __float_as_int(pn.y);
            #pragma unroll
            for (int cc = 0; cc < CH_PER_WARP; ++cc)
                vB[cc] = __ldg(pb + (size_t)cc * PLANE + offBn);
        }

        // epilogue on odd samples: dual-channel shuffle reduction
        if ((i & 1) == 1) {
            const int oy = i >> 1;
            #pragma unroll
            for (int pr = 0; pr < CH_PER_WARP / 2; ++pr) {
                float aL = wx * bacc[2 * pr + 0];   // low half's channel
                float aH = wx * bacc[2 * pr + 1];   // high half's channel
                float t  = hiHalf ? aL : aH;
                float rr = __shfl_xor_sync(0xffffffffu, t, 16);
                float s  = (hiHalf ? aH : aL) + rr;        // corner-folded
                s += __shfl_xor_sync(0xffffffffu, s, 1);   // x-pair fold
                if (doSt) {
                    outB[(size_t)(2 * pr) * (OUT_H * OUT_W) + oy * OUT_W] = s;
                }
            }
        }
    }
}

extern "C" void kernel_launch(void* const* d_in, const int* in_sizes, int n_in,
                              void* d_out, int out_size)
{
    const float* feat = (const float*)d_in[0];
    const float* rois = (const float*)d_in[1];
    float*       out  = (float*)d_out;

    dim3 grid(R, GROUPS);
    dim3 block(WARPS_PER_BLOCK * 32);
    roi_align_kernel<<<grid, block>>>(feat, rois, out);
}